// round 3
// baseline (speedup 1.0000x reference)
#include <cuda_runtime.h>

// ---------------------------------------------------------------------------
// MoE router, fully fused single kernel:
//   logits = X[16384,2048] @ W^T[2048,64]  (fp32, FFMA2 f32x2 packed math)
//   per-token top-2 + softmax weights, full-softmax expert means,
//   top-1 counts -> Switch aux loss (last-block reduction).
// Output f32: [0,32768) indices, [32768,65536) weights, [65536] aux.
// ---------------------------------------------------------------------------

#define TOKENS   16384
#define DDIM     2048
#define NEXP     64
#define BM       128
#define BK       32
#define NITERS   (DDIM / BK)        // 64
#define XTSTR    132                // padded token-stride of transposed X tile
#define WGT_OFF  (2 * TOKENS)
#define AUX_OFF  (4 * TOKENS)
#define AUX_W    0.01f
#define NBLK     (TOKENS / BM)      // 128

__device__ float    g_probsum[NEXP];   // zero-init at load; reset by last block
__device__ int      g_cnt[NEXP];
__device__ unsigned g_arrived;

__device__ __forceinline__ void fma2(unsigned long long& d,
                                     unsigned long long a,
                                     unsigned long long b) {
    asm("fma.rn.f32x2 %0, %1, %2, %0;" : "+l"(d) : "l"(a), "l"(b));
}

struct SmemT {
    union {
        struct {
            float  xt[BK][XTSTR];        // transposed X tile: xt[k][token]
            float2 wdup[BK][NEXP];       // pre-duplicated W: {w,w}
        } ml;
        struct { float logits[BM][NEXP + 1]; } ep;
    } u;
    float tmax[BM];
    float tinv[BM];
    int   scnt[NEXP];
    float red[NEXP];
    int   is_last;
};

__global__ void __launch_bounds__(256, 1)
moe_router_fused(const float* __restrict__ X, const float* __restrict__ W,
                 float* __restrict__ out) {
    __shared__ SmemT s;
    const int tid = threadIdx.x;
    const int T0  = blockIdx.x * BM;

    if (tid < NEXP) s.scnt[tid] = 0;

    // 8 tokens x 4 experts per thread; token pairs packed as f32x2.
    unsigned long long acc[4][4];
#pragma unroll
    for (int j = 0; j < 4; ++j)
#pragma unroll
        for (int i = 0; i < 4; ++i) acc[j][i] = 0ull;

    const int tx = tid & 15;          // expert group (consumers of one x value
    const int ty = tid >> 4;          //   are 16 consecutive threads: broadcast)
    const int e0 = tx * 4;
    const int t0 = ty * 8;

    float4 xr[4], wr[2];              // global-load staging for next K-slab

    // --- prologue: load & store K-slab 0 ---
    {
#pragma unroll
        for (int p = 0; p < 4; ++p) {
            int slot = tid + 256 * p;
            int r = slot >> 3;
            int c = (slot & 7) << 2;
            xr[p] = *(const float4*)(X + (size_t)(T0 + r) * DDIM + c);
        }
#pragma unroll
        for (int p = 0; p < 2; ++p) {
            int slot = tid + 256 * p;
            int e = slot >> 3;
            int c = (slot & 7) << 2;
            wr[p] = *(const float4*)(W + (size_t)e * DDIM + c);
        }
#pragma unroll
        for (int p = 0; p < 4; ++p) {
            int slot = tid + 256 * p;
            int r = slot >> 3;
            int c = (slot & 7) << 2;
            s.u.ml.xt[c + 0][r] = xr[p].x;
            s.u.ml.xt[c + 1][r] = xr[p].y;
            s.u.ml.xt[c + 2][r] = xr[p].z;
            s.u.ml.xt[c + 3][r] = xr[p].w;
        }
#pragma unroll
        for (int p = 0; p < 2; ++p) {
            int slot = tid + 256 * p;
            int e = slot >> 3;
            int c = (slot & 7) << 2;
            s.u.ml.wdup[c + 0][e] = make_float2(wr[p].x, wr[p].x);
            s.u.ml.wdup[c + 1][e] = make_float2(wr[p].y, wr[p].y);
            s.u.ml.wdup[c + 2][e] = make_float2(wr[p].z, wr[p].z);
            s.u.ml.wdup[c + 3][e] = make_float2(wr[p].w, wr[p].w);
        }
        __syncthreads();
    }

    // --- mainloop ---
    for (int it = 0; it < NITERS; ++it) {
        if (it + 1 < NITERS) {        // prefetch next slab into registers
            const int K0 = (it + 1) * BK;
#pragma unroll
            for (int p = 0; p < 4; ++p) {
                int slot = tid + 256 * p;
                int r = slot >> 3;
                int c = (slot & 7) << 2;
                xr[p] = *(const float4*)(X + (size_t)(T0 + r) * DDIM + K0 + c);
            }
#pragma unroll
            for (int p = 0; p < 2; ++p) {
                int slot = tid + 256 * p;
                int e = slot >> 3;
                int c = (slot & 7) << 2;
                wr[p] = *(const float4*)(W + (size_t)e * DDIM + K0 + c);
            }
        }

#pragma unroll
        for (int k = 0; k < BK; ++k) {
            ulonglong2 xa = *(const ulonglong2*)&s.u.ml.xt[k][t0];      // tok t0..+3
            ulonglong2 xb = *(const ulonglong2*)&s.u.ml.xt[k][t0 + 4];  // tok t0+4..+7
            ulonglong2 wa = *(const ulonglong2*)&s.u.ml.wdup[k][e0];     // {w0,w0},{w1,w1}
            ulonglong2 wb = *(const ulonglong2*)&s.u.ml.wdup[k][e0 + 2]; // {w2,w2},{w3,w3}
            fma2(acc[0][0], xa.x, wa.x); fma2(acc[0][1], xa.x, wa.y);
            fma2(acc[0][2], xa.x, wb.x); fma2(acc[0][3], xa.x, wb.y);
            fma2(acc[1][0], xa.y, wa.x); fma2(acc[1][1], xa.y, wa.y);
            fma2(acc[1][2], xa.y, wb.x); fma2(acc[1][3], xa.y, wb.y);
            fma2(acc[2][0], xb.x, wa.x); fma2(acc[2][1], xb.x, wa.y);
            fma2(acc[2][2], xb.x, wb.x); fma2(acc[2][3], xb.x, wb.y);
            fma2(acc[3][0], xb.y, wa.x); fma2(acc[3][1], xb.y, wa.y);
            fma2(acc[3][2], xb.y, wb.x); fma2(acc[3][3], xb.y, wb.y);
        }

        __syncthreads();
        if (it + 1 < NITERS) {
#pragma unroll
            for (int p = 0; p < 4; ++p) {
                int slot = tid + 256 * p;
                int r = slot >> 3;
                int c = (slot & 7) << 2;
                s.u.ml.xt[c + 0][r] = xr[p].x;
                s.u.ml.xt[c + 1][r] = xr[p].y;
                s.u.ml.xt[c + 2][r] = xr[p].z;
                s.u.ml.xt[c + 3][r] = xr[p].w;
            }
#pragma unroll
            for (int p = 0; p < 2; ++p) {
                int slot = tid + 256 * p;
                int e = slot >> 3;
                int c = (slot & 7) << 2;
                s.u.ml.wdup[c + 0][e] = make_float2(wr[p].x, wr[p].x);
                s.u.ml.wdup[c + 1][e] = make_float2(wr[p].y, wr[p].y);
                s.u.ml.wdup[c + 2][e] = make_float2(wr[p].z, wr[p].z);
                s.u.ml.wdup[c + 3][e] = make_float2(wr[p].w, wr[p].w);
            }
            __syncthreads();
        }
    }

    // --- epilogue: dump logits to smem ---
#pragma unroll
    for (int j = 0; j < 4; ++j)
#pragma unroll
        for (int i = 0; i < 4; ++i) {
            union { unsigned long long u; float2 f; } cv;
            cv.u = acc[j][i];
            s.u.ep.logits[t0 + 2 * j + 0][e0 + i] = cv.f.x;
            s.u.ep.logits[t0 + 2 * j + 1][e0 + i] = cv.f.y;
        }
    __syncthreads();

    // per-token top-2 (stable: lowest index wins ties, matching lax.top_k)
    if (tid < BM) {
        const int t = tid;
        float m1 = -3.4e38f, m2 = -3.4e38f;
        int   i1 = 0, i2 = 0;
#pragma unroll 8
        for (int e = 0; e < NEXP; ++e) {
            float l = s.u.ep.logits[t][e];
            if (l > m1) { m2 = m1; i2 = i1; m1 = l; i1 = e; }
            else if (l > m2) { m2 = l; i2 = e; }
        }
        float sum = 0.0f;
#pragma unroll 8
        for (int e = 0; e < NEXP; ++e)
            sum += __expf(s.u.ep.logits[t][e] - m1);
        s.tmax[t] = m1;
        s.tinv[t] = 1.0f / sum;

        const int T = T0 + t;
        float d  = expf(m2 - m1);
        float w1 = 1.0f / (1.0f + d);
        out[2 * T + 0] = (float)i1;
        out[2 * T + 1] = (float)i2;
        out[WGT_OFF + 2 * T + 0] = w1;
        out[WGT_OFF + 2 * T + 1] = d * w1;

        atomicAdd(&s.scnt[i1], 1);
    }
    __syncthreads();

    // per-expert probability partials: 4 row-groups x 64 experts
    {
        const int g = tid >> 6;
        const int e = tid & 63;
        float partial = 0.0f;
        const int tb = g * 32;
#pragma unroll 8
        for (int t = tb; t < tb + 32; ++t)
            partial += __expf(s.u.ep.logits[t][e] - s.tmax[t]) * s.tinv[t];
        atomicAdd(&g_probsum[e], partial);
    }
    if (tid < NEXP) atomicAdd(&g_cnt[tid], s.scnt[tid]);

    // --- cross-block finalize: last block computes aux loss + resets state ---
    __threadfence();
    if (tid == 0) {
        unsigned old = atomicAdd(&g_arrived, 1u);
        s.is_last = (old == NBLK - 1);
    }
    __syncthreads();
    if (!s.is_last) return;

    if (tid < NEXP) {
        float p = __ldcg(&g_probsum[tid]);
        int   c = __ldcg(&g_cnt[tid]);
        s.red[tid] = p * (float)c;
    }
    __syncthreads();
    if (tid == 0) {
        float sacc = 0.0f;
#pragma unroll
        for (int i = 0; i < NEXP; ++i) sacc += s.red[i];
        const float invN = 1.0f / (float)TOKENS;
        out[AUX_OFF] = (float)NEXP * sacc * invN * invN * AUX_W;
        g_arrived = 0u;
    }
    if (tid < NEXP) { g_probsum[tid] = 0.0f; g_cnt[tid] = 0; }
}

extern "C" void kernel_launch(void* const* d_in, const int* in_sizes, int n_in,
                              void* d_out, int out_size) {
    const float* X = (const float*)d_in[0];   // [4,4096,2048] f32
    const float* W = (const float*)d_in[1];   // [64,2048] f32
    float* out = (float*)d_out;               // 65537 f32

    moe_router_fused<<<NBLK, 256>>>(X, W, out);
}

// round 4
// speedup vs baseline: 1.1755x; 1.1755x over previous
#include <cuda_runtime.h>

// ---------------------------------------------------------------------------
// MoE router, fused single kernel, round 4:
//   logits = X[16384,2048] @ W^T[2048,64]  (fp32 FFMA2, expert-packed pairs)
//   X: cp.async row-major (no transpose, no staging); W: reg-transposed, swizzled.
//   16 warps/CTA, 1 CTA/SM, double-buffered BK=16 slabs.
// Output f32: [0,32768) indices, [32768,65536) weights, [65536] aux.
// ---------------------------------------------------------------------------

#define TOKENS   16384
#define DDIM     2048
#define NEXP     64
#define BM       128
#define BK       16
#define NSLAB    (DDIM / BK)     // 128
#define XSTR     20              // floats per x row (80B, 16B-aligned, bank-spread)
#define WSTR     96              // floats per w row (swizzled pair layout)
#define LSTR     66              // logits row stride
#define NTHR     512
#define NBLK     (TOKENS / BM)   // 128
#define WGT_OFF  (2 * TOKENS)
#define AUX_OFF  (4 * TOKENS)
#define AUX_W    0.01f

typedef unsigned long long ull;

__device__ float    g_probsum[NEXP];
__device__ int      g_cnt[NEXP];
__device__ unsigned g_arrived;

__device__ __forceinline__ void fma2(ull& d, ull a, ull b) {
    asm("fma.rn.f32x2 %0, %1, %2, %0;" : "+l"(d) : "l"(a), "l"(b));
}
__device__ __forceinline__ ull dup2(float v) {
    ull r;
    asm("mov.b64 %0, {%1, %1};" : "=l"(r) : "f"(v));
    return r;
}
__device__ __forceinline__ unsigned su32(const void* p) {
    return (unsigned)__cvta_generic_to_shared(p);
}
__device__ __forceinline__ void cp16(unsigned dst, const void* src) {
    asm volatile("cp.async.cg.shared.global [%0], [%1], 16;" :: "r"(dst), "l"(src));
}

struct Smem {
    union {
        struct {
            float x[2][BM][XSTR];   // row-major X slabs (cp.async target)
            float w[2][BK][WSTR];   // swizzled, k-major W slabs
        } ml;
        float logits[BM][LSTR];
    } u;
    float tmax[BM];
    float tinv[BM];
    int   scnt[NEXP];
    float red[NEXP];
    int   is_last;
};

__global__ void __launch_bounds__(NTHR, 1)
moe_router(const float* __restrict__ X, const float* __restrict__ W,
           float* __restrict__ out) {
    __shared__ Smem s;
    const int tid = threadIdx.x;
    const int T0  = blockIdx.x * BM;

    if (tid < NEXP) s.scnt[tid] = 0;

    // thread tile: 2 tokens x 8 experts (4 f32x2 expert pairs)
    const int tx = tid & 7;            // expert octet (8 lanes broadcast x)
    const int ty = tid >> 3;           // token pair id 0..63
    const int e0 = tx * 8;
    const int t0 = ty * 2;
    const int wf = 12 * tx;            // swizzled float offset of this octet's pairs

    // cp.async map: token ct = tid>>2, 16B chunk cc = (tid&3)*4
    const int ct = tid >> 2;
    const int cc = (tid & 3) * 4;
    const float* xsrc = X + (size_t)(T0 + ct) * DDIM + cc;

    // W map: expert we = tid&63, k-chunk wk = (tid>>6)*2
    const int we = tid & 63;
    const int wk = (tid >> 6) * 2;
    const float* wsrc = W + (size_t)we * DDIM + wk;
    // swizzled store index: pair p = we>>1 stored at p + 2*(p>>2)
    const int wsi = we + 4 * (we >> 3);   // = 2p + 4(p>>2) + (we&1)

    ull acc[2][4];
#pragma unroll
    for (int j = 0; j < 2; ++j)
#pragma unroll
        for (int i = 0; i < 4; ++i) acc[j][i] = 0ull;

    // --- prologue: slab 0 ---
    cp16(su32(&s.u.ml.x[0][ct][cc]), xsrc);
    asm volatile("cp.async.commit_group;" ::: "memory");
    {
        float2 wld = *(const float2*)wsrc;
        s.u.ml.w[0][wk + 0][wsi] = wld.x;
        s.u.ml.w[0][wk + 1][wsi] = wld.y;
    }
    asm volatile("cp.async.wait_group 0;" ::: "memory");
    __syncthreads();

    // --- mainloop: 128 double-buffered slabs ---
    float2 wld;
    for (int it = 0; it < NSLAB; ++it) {
        const int buf  = it & 1;
        const int nbuf = buf ^ 1;
        if (it + 1 < NSLAB) {
            const int K0 = (it + 1) * BK;
            cp16(su32(&s.u.ml.x[nbuf][ct][cc]), xsrc + K0);
            asm volatile("cp.async.commit_group;" ::: "memory");
            wld = *(const float2*)(wsrc + K0);
        }

#pragma unroll
        for (int k = 0; k < BK; ++k) {
            const float* wrow = &s.u.ml.w[buf][k][0];
            ulonglong2 wA = *(const ulonglong2*)(wrow + wf);       // pairs 4tx,4tx+1
            ulonglong2 wB = *(const ulonglong2*)(wrow + wf + 4);   // pairs 4tx+2,4tx+3
            ull xd0 = dup2(s.u.ml.x[buf][t0 + 0][k]);
            ull xd1 = dup2(s.u.ml.x[buf][t0 + 1][k]);
            fma2(acc[0][0], xd0, wA.x); fma2(acc[0][1], xd0, wA.y);
            fma2(acc[0][2], xd0, wB.x); fma2(acc[0][3], xd0, wB.y);
            fma2(acc[1][0], xd1, wA.x); fma2(acc[1][1], xd1, wA.y);
            fma2(acc[1][2], xd1, wB.x); fma2(acc[1][3], xd1, wB.y);
        }

        if (it + 1 < NSLAB) {
            s.u.ml.w[nbuf][wk + 0][wsi] = wld.x;
            s.u.ml.w[nbuf][wk + 1][wsi] = wld.y;
            asm volatile("cp.async.wait_group 0;" ::: "memory");
        }
        __syncthreads();
    }

    // --- dump logits: float2 per expert pair ---
#pragma unroll
    for (int j = 0; j < 2; ++j)
#pragma unroll
        for (int i = 0; i < 4; ++i) {
            union { ull u; float2 f; } cv;
            cv.u = acc[j][i];
            *(float2*)&s.u.logits[t0 + j][e0 + 2 * i] = cv.f;
        }
    __syncthreads();

    // --- per-token top-2 (stable: lowest index wins ties) + normalizer ---
    if (tid < BM) {
        const int t = tid;
        float m1 = -3.4e38f, m2 = -3.4e38f;
        int   i1 = 0, i2 = 0;
#pragma unroll 8
        for (int e = 0; e < NEXP; ++e) {
            float l = s.u.logits[t][e];
            if (l > m1) { m2 = m1; i2 = i1; m1 = l; i1 = e; }
            else if (l > m2) { m2 = l; i2 = e; }
        }
        float sum = 0.0f;
#pragma unroll 8
        for (int e = 0; e < NEXP; ++e)
            sum += __expf(s.u.logits[t][e] - m1);
        s.tmax[t] = m1;
        s.tinv[t] = 1.0f / sum;

        const int T = T0 + t;
        float d  = expf(m2 - m1);
        float w1 = 1.0f / (1.0f + d);
        out[2 * T + 0] = (float)i1;
        out[2 * T + 1] = (float)i2;
        out[WGT_OFF + 2 * T + 0] = w1;
        out[WGT_OFF + 2 * T + 1] = d * w1;

        atomicAdd(&s.scnt[i1], 1);
    }
    __syncthreads();

    // --- per-expert probability partials: 8 row-groups x 64 experts ---
    {
        const int g = tid >> 6;          // 0..7
        const int e = tid & 63;
        const int tb = g * 16;
        float partial = 0.0f;
#pragma unroll 8
        for (int t = tb; t < tb + 16; ++t)
            partial += __expf(s.u.logits[t][e] - s.tmax[t]) * s.tinv[t];
        atomicAdd(&g_probsum[e], partial);
    }
    if (tid < NEXP) atomicAdd(&g_cnt[tid], s.scnt[tid]);

    // --- last-block finalize: aux loss + state reset for graph replay ---
    __threadfence();
    if (tid == 0) {
        unsigned old = atomicAdd(&g_arrived, 1u);
        s.is_last = (old == NBLK - 1);
    }
    __syncthreads();
    if (!s.is_last) return;
    __threadfence();

    if (tid < NEXP) {
        float p = __ldcg(&g_probsum[tid]);
        int   c = __ldcg(&g_cnt[tid]);
        s.red[tid] = p * (float)c;
    }
    __syncthreads();
    if (tid == 0) {
        float sacc = 0.0f;
#pragma unroll
        for (int i = 0; i < NEXP; ++i) sacc += s.red[i];
        const float invN = 1.0f / (float)TOKENS;
        out[AUX_OFF] = (float)NEXP * sacc * invN * invN * AUX_W;
        g_arrived = 0u;
    }
    if (tid < NEXP) { g_probsum[tid] = 0.0f; g_cnt[tid] = 0; }
}

extern "C" void kernel_launch(void* const* d_in, const int* in_sizes, int n_in,
                              void* d_out, int out_size) {
    const float* X = (const float*)d_in[0];   // [4,4096,2048] f32
    const float* W = (const float*)d_in[1];   // [64,2048] f32
    float* out = (float*)d_out;               // 65537 f32

    moe_router<<<NBLK, NTHR>>>(X, W, out);
}

// round 6
// speedup vs baseline: 2.0805x; 1.7698x over previous
#include <cuda_runtime.h>

// ---------------------------------------------------------------------------
// MoE router, round 6: split-K FFMA2 GEMM at 1.0 B/MAC shared traffic.
//   grid = 64 token-tiles x 2 K-halves. Each CTA: 256 thr, BM=256, 8tok x 8exp
//   per thread (64 MACs), expert-pair-packed f32x2 accumulators.
//   Partial logits -> 8MB device scratch; second CTA per tile sums + epilogue.
//   (r5 fix: LSTR 66->68 for float4 alignment; alignas(16) scratch.)
// Output f32: [0,32768) indices, [32768,65536) weights, [65536] aux.
// ---------------------------------------------------------------------------

#define TOKENS   16384
#define DDIM     2048
#define NEXP     64
#define BM       256
#define BK       16
#define KSPLIT   2
#define KHALF    (DDIM / KSPLIT)    // 1024
#define NSLAB    (KHALF / BK)       // 64
#define NTILE    (TOKENS / BM)      // 64
#define NTHR     256
#define XSTR     20                 // x row stride (floats)
#define WSTR     96                 // swizzled w row stride (floats)
#define LSTR     68                 // logits row stride (272B, 16B-aligned)
#define WGT_OFF  (2 * TOKENS)
#define AUX_OFF  (4 * TOKENS)
#define AUX_W    0.01f

typedef unsigned long long ull;

__device__ alignas(16) float g_part[KSPLIT][NTILE][BM][NEXP];   // 8 MB partials
__device__ int      g_tile_cnt[NTILE];
__device__ float    g_probsum[NEXP];
__device__ int      g_cnt[NEXP];
__device__ unsigned g_arrived;

__device__ __forceinline__ void fma2(ull& d, ull a, ull b) {
    asm("fma.rn.f32x2 %0, %1, %2, %0;" : "+l"(d) : "l"(a), "l"(b));
}
__device__ __forceinline__ ull dup2(float v) {
    ull r;
    asm("mov.b64 %0, {%1, %1};" : "=l"(r) : "f"(v));
    return r;
}
__device__ __forceinline__ unsigned su32(const void* p) {
    return (unsigned)__cvta_generic_to_shared(p);
}
__device__ __forceinline__ void cp16(unsigned dst, const void* src) {
    asm volatile("cp.async.cg.shared.global [%0], [%1], 16;" :: "r"(dst), "l"(src));
}

struct Smem {
    union {
        struct {
            float x[2][BM][XSTR];     // 40960 B  (cp.async target, row-major)
            float w[2][BK][WSTR];     // 12288 B  (swizzled expert pairs)
        } ml;
        struct { float logits[BM][LSTR]; } ep;   // 69632 B
    } u;
    float tmax[BM];
    float tinv[BM];
    int   scnt[NEXP];
    float red[NEXP];
    int   flag;
};

__global__ void __launch_bounds__(NTHR, 1)
moe_router(const float* __restrict__ X, const float* __restrict__ W,
           float* __restrict__ out) {
    extern __shared__ char raw[];
    Smem& s = *reinterpret_cast<Smem*>(raw);

    const int tid  = threadIdx.x;
    const int tile = blockIdx.x >> 1;
    const int kh   = blockIdx.x & 1;
    const int T0   = tile * BM;
    const int Kb   = kh * KHALF;

    // thread tile: tokens {ty + 32j, j=0..7} x experts [8tx, 8tx+8)
    const int tx = tid & 7;
    const int ty = tid >> 3;
    const int e0 = tx * 8;
    const int wf = 12 * tx;            // swizzled float offset of 4 expert pairs

    // cp.async x map: 4 chunks of 16B per thread per slab
    const float* xsrc[4];
    unsigned     xdst[2][4];
#pragma unroll
    for (int p = 0; p < 4; ++p) {
        int slot = tid + NTHR * p;
        int row  = slot >> 2;
        int cc   = (slot & 3) << 2;
        xsrc[p] = X + (size_t)(T0 + row) * DDIM + Kb + cc;
        xdst[0][p] = su32(&s.u.ml.x[0][row][cc]);
        xdst[1][p] = su32(&s.u.ml.x[1][row][cc]);
    }

    // w map: expert we, 4 consecutive k's; swizzled store index
    const int we  = tid & 63;
    const int wk  = (tid >> 6) * 4;
    const int wsi = we + 4 * (we >> 3);
    const float* wsrc = W + (size_t)we * DDIM + Kb + wk;

    ull acc[8][4];
#pragma unroll
    for (int j = 0; j < 8; ++j)
#pragma unroll
        for (int i = 0; i < 4; ++i) acc[j][i] = 0ull;

    // --- prologue: slab 0 ---
#pragma unroll
    for (int p = 0; p < 4; ++p) cp16(xdst[0][p], xsrc[p]);
    asm volatile("cp.async.commit_group;" ::: "memory");
    {
        float4 wl = *(const float4*)wsrc;
        s.u.ml.w[0][wk + 0][wsi] = wl.x;
        s.u.ml.w[0][wk + 1][wsi] = wl.y;
        s.u.ml.w[0][wk + 2][wsi] = wl.z;
        s.u.ml.w[0][wk + 3][wsi] = wl.w;
    }
    asm volatile("cp.async.wait_group 0;" ::: "memory");
    __syncthreads();

    // --- mainloop over 64 double-buffered K-slabs ---
    float4 wl;
    for (int it = 0; it < NSLAB; ++it) {
        const int buf  = it & 1;
        const int nbuf = buf ^ 1;
        if (it + 1 < NSLAB) {
            const int K0 = (it + 1) * BK;
#pragma unroll
            for (int p = 0; p < 4; ++p) cp16(xdst[nbuf][p], xsrc[p] + K0);
            asm volatile("cp.async.commit_group;" ::: "memory");
            wl = *(const float4*)(wsrc + K0);
        }

#pragma unroll
        for (int kk = 0; kk < BK / 2; ++kk) {
            float2 xv[8];
#pragma unroll
            for (int j = 0; j < 8; ++j)
                xv[j] = *(const float2*)&s.u.ml.x[buf][ty + 32 * j][2 * kk];
#pragma unroll
            for (int h = 0; h < 2; ++h) {
                const float* wrow = s.u.ml.w[buf][2 * kk + h];
                ulonglong2 wA = *(const ulonglong2*)(wrow + wf);
                ulonglong2 wB = *(const ulonglong2*)(wrow + wf + 4);
#pragma unroll
                for (int j = 0; j < 8; ++j) {
                    ull xd = dup2(h ? xv[j].y : xv[j].x);
                    fma2(acc[j][0], xd, wA.x);
                    fma2(acc[j][1], xd, wA.y);
                    fma2(acc[j][2], xd, wB.x);
                    fma2(acc[j][3], xd, wB.y);
                }
            }
        }

        if (it + 1 < NSLAB) {
            s.u.ml.w[nbuf][wk + 0][wsi] = wl.x;
            s.u.ml.w[nbuf][wk + 1][wsi] = wl.y;
            s.u.ml.w[nbuf][wk + 2][wsi] = wl.z;
            s.u.ml.w[nbuf][wk + 3][wsi] = wl.w;
            asm volatile("cp.async.wait_group 0;" ::: "memory");
        }
        __syncthreads();
    }

    // --- write partial logits (deterministic: exactly 2 addends per logit) ---
#pragma unroll
    for (int j = 0; j < 8; ++j) {
        const int tok = ty + 32 * j;
        ulonglong2* dst = (ulonglong2*)&g_part[kh][tile][tok][e0];
        dst[0] = make_ulonglong2(acc[j][0], acc[j][1]);
        dst[1] = make_ulonglong2(acc[j][2], acc[j][3]);
    }
    __threadfence();
    if (tid == 0) {
        int old = atomicAdd(&g_tile_cnt[tile], 1);
        s.flag = (old == 1);
    }
    __syncthreads();
    if (!s.flag) return;            // first CTA of the pair exits
    __threadfence();

    // ===================== epilogue (second CTA of the tile) ====================
    if (tid == 0) g_tile_cnt[tile] = 0;       // reset for graph replay
    if (tid < NEXP) s.scnt[tid] = 0;
    __syncthreads();

    // combine halves; keep logits in regs AND mirror to smem for phase 2
    const int t = tid;
    float lg[NEXP];
    {
        const float4* p0 = (const float4*)&g_part[0][tile][t][0];
        const float4* p1 = (const float4*)&g_part[1][tile][t][0];
#pragma unroll
        for (int c = 0; c < NEXP / 4; ++c) {
            float4 a = __ldcg(p0 + c);
            float4 b = __ldcg(p1 + c);
            float4 sm = make_float4(a.x + b.x, a.y + b.y, a.z + b.z, a.w + b.w);
            lg[4 * c + 0] = sm.x; lg[4 * c + 1] = sm.y;
            lg[4 * c + 2] = sm.z; lg[4 * c + 3] = sm.w;
            *(float4*)&s.u.ep.logits[t][4 * c] = sm;
        }
    }

    // top-2 (stable: strict >, lowest index wins ties) + full-softmax normalizer
    {
        float m1 = -3.4e38f, m2 = -3.4e38f;
        int   i1 = 0, i2 = 0;
#pragma unroll
        for (int e = 0; e < NEXP; ++e) {
            float l = lg[e];
            if (l > m1) { m2 = m1; i2 = i1; m1 = l; i1 = e; }
            else if (l > m2) { m2 = l; i2 = e; }
        }
        float sum = 0.0f;
#pragma unroll
        for (int e = 0; e < NEXP; ++e) sum += __expf(lg[e] - m1);
        s.tmax[t] = m1;
        s.tinv[t] = 1.0f / sum;

        const int T = T0 + t;
        float d  = expf(m2 - m1);
        float w1 = 1.0f / (1.0f + d);
        out[2 * T + 0] = (float)i1;
        out[2 * T + 1] = (float)i2;
        out[WGT_OFF + 2 * T + 0] = w1;
        out[WGT_OFF + 2 * T + 1] = d * w1;

        atomicAdd(&s.scnt[i1], 1);
    }
    __syncthreads();

    // per-expert probability partials: 4 row-groups x 64 experts x 64 tokens
    {
        const int g  = tid >> 6;
        const int e  = tid & 63;
        const int tb = g * 64;
        float partial = 0.0f;
#pragma unroll 8
        for (int tt = tb; tt < tb + 64; ++tt)
            partial += __expf(s.u.ep.logits[tt][e] - s.tmax[tt]) * s.tinv[tt];
        atomicAdd(&g_probsum[e], partial);
    }
    if (tid < NEXP) atomicAdd(&g_cnt[tid], s.scnt[tid]);

    // --- global finalize: last epilogue CTA computes aux loss + resets ---
    __threadfence();
    if (tid == 0) {
        unsigned old = atomicAdd(&g_arrived, 1u);
        s.flag = (old == NTILE - 1);
    }
    __syncthreads();
    if (!s.flag) return;
    __threadfence();

    if (tid < NEXP) {
        float p = __ldcg(&g_probsum[tid]);
        int   c = __ldcg(&g_cnt[tid]);
        s.red[tid] = p * (float)c;
    }
    __syncthreads();
    if (tid == 0) {
        float sacc = 0.0f;
#pragma unroll
        for (int i = 0; i < NEXP; ++i) sacc += s.red[i];
        const float invN = 1.0f / (float)TOKENS;
        out[AUX_OFF] = (float)NEXP * sacc * invN * invN * AUX_W;
        g_arrived = 0u;
    }
    if (tid < NEXP) { g_probsum[tid] = 0.0f; g_cnt[tid] = 0; }
}

extern "C" void kernel_launch(void* const* d_in, const int* in_sizes, int n_in,
                              void* d_out, int out_size) {
    const float* X = (const float*)d_in[0];   // [4,4096,2048] f32
    const float* W = (const float*)d_in[1];   // [64,2048] f32
    float* out = (float*)d_out;               // 65537 f32

    static_assert(sizeof(Smem) <= 80 * 1024, "smem");
    cudaFuncSetAttribute(moe_router, cudaFuncAttributeMaxDynamicSharedMemorySize,
                         (int)sizeof(Smem));
    moe_router<<<NTILE * KSPLIT, NTHR, sizeof(Smem)>>>(X, W, out);
}